// round 1
// baseline (speedup 1.0000x reference)
#include <cuda_runtime.h>
#include <cuda_bf16.h>

// Problem constants (fixed shapes from reference)
#define B 64
#define C 256
#define HW 3136          // 56*56
#define HW4 784          // HW/4 float4 per plane
#define R 16             // reduced dim
#define POSITION 205     // round(0.8*256); thresh = sorted[POSITION-1] (0-idx 204)

__device__ float g_y[B * C];     // pooled means
__device__ float g_mask[B * C];  // 0/1 mask

// ---------------------------------------------------------------------------
// Kernel 1: global average pool. One block per (b,c) plane.
// ---------------------------------------------------------------------------
__global__ void pool_kernel(const float* __restrict__ x) {
    const int plane = blockIdx.x;                 // b*C + c
    const float4* __restrict__ p = (const float4*)(x + (size_t)plane * HW);
    float s = 0.f;
    for (int i = threadIdx.x; i < HW4; i += blockDim.x) {
        float4 v = p[i];
        s += v.x + v.y + v.z + v.w;
    }
    // warp reduce
    #pragma unroll
    for (int off = 16; off > 0; off >>= 1)
        s += __shfl_xor_sync(0xFFFFFFFFu, s, off);
    __shared__ float warp_sums[8];
    const int wid = threadIdx.x >> 5, lid = threadIdx.x & 31;
    if (lid == 0) warp_sums[wid] = s;
    __syncthreads();
    if (wid == 0) {
        s = (lid < (blockDim.x >> 5)) ? warp_sums[lid] : 0.f;
        #pragma unroll
        for (int off = 4; off > 0; off >>= 1)
            s += __shfl_xor_sync(0xFFFFFFFFu, s, off);
        if (lid == 0) g_y[plane] = s * (1.0f / (float)HW);
    }
}

// ---------------------------------------------------------------------------
// Kernel 2: SE MLP + rank-select threshold + mask. One block per batch row.
// 256 threads.
// ---------------------------------------------------------------------------
__global__ void se_mask_kernel(const float* __restrict__ W1,   // [R, C]
                               const float* __restrict__ W2) { // [C, R]
    const int b = blockIdx.x;
    const int tid = threadIdx.x;
    __shared__ float sy[C];
    __shared__ float sh[R];
    __shared__ float sz[C];
    __shared__ float sthresh;

    sy[tid] = g_y[b * C + tid];
    __syncthreads();

    // hidden = relu(y @ W1^T): 8 warps, each computes 2 of the 16 rows
    const int wid = tid >> 5, lid = tid & 31;
    #pragma unroll
    for (int rr = 0; rr < 2; rr++) {
        const int row = wid * 2 + rr;
        float s = 0.f;
        for (int i = lid; i < C; i += 32)
            s += sy[i] * W1[row * C + i];
        #pragma unroll
        for (int off = 16; off > 0; off >>= 1)
            s += __shfl_xor_sync(0xFFFFFFFFu, s, off);
        if (lid == 0) sh[row] = fmaxf(s, 0.f);
    }
    __syncthreads();

    // z = sigmoid(hidden @ W2^T): one channel per thread
    float s = 0.f;
    #pragma unroll
    for (int k = 0; k < R; k++)
        s += sh[k] * W2[tid * R + k];
    const float z = 1.0f / (1.0f + __expf(-s));
    sz[tid] = z;
    __syncthreads();

    // rank-select: thresh = sorted[POSITION-1]. Element v is at 0-indexed
    // position 204 iff (#less < v) <= 204 and (#<= v) >= 205.
    int lt = 0, le = 0;
    for (int j = 0; j < C; j++) {
        const float zj = sz[j];
        lt += (zj < z);
        le += (zj <= z);
    }
    if (lt <= (POSITION - 1) && le >= POSITION) sthresh = z;
    __syncthreads();

    g_mask[b * C + tid] = (z <= sthresh) ? 1.0f : 0.0f;
}

// ---------------------------------------------------------------------------
// Kernel 3: out = x * mask[b,c], float4 vectorized.
// ---------------------------------------------------------------------------
__global__ void apply_mask_kernel(const float* __restrict__ x,
                                  float* __restrict__ out) {
    const int n4 = B * C * HW4;
    int i = blockIdx.x * blockDim.x + threadIdx.x;
    if (i >= n4) return;
    const float m = __ldg(&g_mask[i / HW4]);
    float4 v = ((const float4*)x)[i];
    v.x *= m; v.y *= m; v.z *= m; v.w *= m;
    ((float4*)out)[i] = v;
}

// ---------------------------------------------------------------------------
extern "C" void kernel_launch(void* const* d_in, const int* in_sizes, int n_in,
                              void* d_out, int out_size) {
    const float* x  = (const float*)d_in[0];
    const float* W1 = (const float*)d_in[1];
    const float* W2 = (const float*)d_in[2];
    float* out = (float*)d_out;

    pool_kernel<<<B * C, 256>>>(x);
    se_mask_kernel<<<B, C>>>(W1, W2);
    const int n4 = B * C * HW4;
    apply_mask_kernel<<<(n4 + 255) / 256, 256>>>(x, out);
}

// round 6
// speedup vs baseline: 1.0818x; 1.0818x over previous
#include <cuda_runtime.h>
#include <cuda_bf16.h>

// Problem constants (fixed shapes from reference)
#define B 64
#define C 256
#define HW 3136          // 56*56
#define HW4 784          // HW/4 float4 per plane
#define R 16             // reduced dim
#define POSITION 205     // round(0.8*256); thresh = sorted[POSITION-1] (0-idx 204)

__device__ float g_y[B * C];     // pooled means
__device__ float g_mask[B * C];  // 0/1 mask

// ---------------------------------------------------------------------------
// Kernel 1: global average pool. One WARP per (b,c) plane; 8 planes per block.
// Each lane issues 24-25 independent float4 loads (high MLP), then a pure
// shfl reduce — no shared memory, no block barrier.
// ---------------------------------------------------------------------------
__global__ void pool_kernel(const float* __restrict__ x) {
    const int wid = threadIdx.x >> 5, lid = threadIdx.x & 31;
    const int plane = blockIdx.x * 8 + wid;       // b*C + c
    const float4* __restrict__ p = (const float4*)(x + (size_t)plane * HW);

    float s = 0.f;
    // 784 = 32*24 + 16
    #pragma unroll
    for (int k = 0; k < 24; k++) {
        float4 v = __ldcs(&p[lid + 32 * k]);
        s += (v.x + v.y) + (v.z + v.w);
    }
    if (lid < 16) {
        float4 v = __ldcs(&p[768 + lid]);
        s += (v.x + v.y) + (v.z + v.w);
    }
    #pragma unroll
    for (int off = 16; off > 0; off >>= 1)
        s += __shfl_xor_sync(0xFFFFFFFFu, s, off);
    if (lid == 0) g_y[plane] = s * (1.0f / (float)HW);
}

// ---------------------------------------------------------------------------
// Kernel 2: SE MLP + rank-select threshold + mask. One block per batch row.
// 256 threads.
// ---------------------------------------------------------------------------
__global__ void se_mask_kernel(const float* __restrict__ W1,   // [R, C]
                               const float* __restrict__ W2) { // [C, R]
    const int b = blockIdx.x;
    const int tid = threadIdx.x;
    __shared__ float sy[C];
    __shared__ float sh[R];
    __shared__ float sz[C];
    __shared__ float sthresh;

    sy[tid] = g_y[b * C + tid];
    __syncthreads();

    // hidden = relu(y @ W1^T): 8 warps, each computes 2 of the 16 rows
    const int wid = tid >> 5, lid = tid & 31;
    #pragma unroll
    for (int rr = 0; rr < 2; rr++) {
        const int row = wid * 2 + rr;
        float s = 0.f;
        for (int i = lid; i < C; i += 32)
            s += sy[i] * W1[row * C + i];
        #pragma unroll
        for (int off = 16; off > 0; off >>= 1)
            s += __shfl_xor_sync(0xFFFFFFFFu, s, off);
        if (lid == 0) sh[row] = fmaxf(s, 0.f);
    }
    __syncthreads();

    // z = sigmoid(hidden @ W2^T): one channel per thread
    float s = 0.f;
    #pragma unroll
    for (int k = 0; k < R; k++)
        s += sh[k] * W2[tid * R + k];
    const float z = 1.0f / (1.0f + __expf(-s));
    sz[tid] = z;
    __syncthreads();

    // rank-select: thresh = sorted[POSITION-1]. Element v is at 0-indexed
    // position 204 iff (#less < v) <= 204 and (#<= v) >= 205.
    int lt = 0, le = 0;
    for (int j = 0; j < C; j++) {
        const float zj = sz[j];
        lt += (zj < z);
        le += (zj <= z);
    }
    if (lt <= (POSITION - 1) && le >= POSITION) sthresh = z;
    __syncthreads();

    g_mask[b * C + tid] = (z <= sthresh) ? 1.0f : 0.0f;
}

// ---------------------------------------------------------------------------
// Kernel 3: out = x * mask[plane]. One block per plane: division-free,
// uniform mask load, streaming loads/stores (no reuse of x or out).
// ---------------------------------------------------------------------------
__global__ void apply_mask_kernel(const float* __restrict__ x,
                                  float* __restrict__ out) {
    const int plane = blockIdx.x;
    const float m = g_mask[plane];
    const float4* __restrict__ px = (const float4*)(x + (size_t)plane * HW);
    float4* __restrict__ po = (float4*)(out + (size_t)plane * HW);
    const int tid = threadIdx.x;

    // 784 = 3*256 + 16
    #pragma unroll
    for (int k = 0; k < 3; k++) {
        const int i = tid + 256 * k;
        float4 v = __ldcs(&px[i]);
        v.x *= m; v.y *= m; v.z *= m; v.w *= m;
        __stcs(&po[i], v);
    }
    if (tid < 16) {
        const int i = 768 + tid;
        float4 v = __ldcs(&px[i]);
        v.x *= m; v.y *= m; v.z *= m; v.w *= m;
        __stcs(&po[i], v);
    }
}

// ---------------------------------------------------------------------------
extern "C" void kernel_launch(void* const* d_in, const int* in_sizes, int n_in,
                              void* d_out, int out_size) {
    const float* x  = (const float*)d_in[0];
    const float* W1 = (const float*)d_in[1];
    const float* W2 = (const float*)d_in[2];
    float* out = (float*)d_out;

    pool_kernel<<<B * C / 8, 256>>>(x);
    se_mask_kernel<<<B, C>>>(W1, W2);
    apply_mask_kernel<<<B * C, 256>>>(x, out);
}

// round 14
// speedup vs baseline: 1.1778x; 1.0887x over previous
#include <cuda_runtime.h>
#include <cuda_bf16.h>

// Problem constants (fixed shapes from reference)
#define B 64
#define C 256
#define HW 3136          // 56*56
#define HW4 784          // HW/4 float4 per plane
#define R 16             // reduced dim
#define POSITION 205     // round(0.8*256); thresh = sorted[POSITION-1] (0-idx 204)
#define NPLANES (B * C)

__device__ float g_y[B * C];     // pooled means
__device__ float g_mask[B * C];  // 0/1 mask

// ---------------------------------------------------------------------------
// Kernel 1: global average pool. One WARP per (b,c) plane; 8 planes per block.
// NORMAL (caching) loads: after this kernel, L2 (~126MB) retains the TAIL of
// x, which the reversed apply kernel consumes first.
// ---------------------------------------------------------------------------
__global__ void pool_kernel(const float* __restrict__ x) {
    const int wid = threadIdx.x >> 5, lid = threadIdx.x & 31;
    const int plane = blockIdx.x * 8 + wid;       // b*C + c
    const float4* __restrict__ p = (const float4*)(x + (size_t)plane * HW);

    float s = 0.f;
    // 784 = 32*24 + 16
    #pragma unroll
    for (int k = 0; k < 24; k++) {
        float4 v = p[lid + 32 * k];
        s += (v.x + v.y) + (v.z + v.w);
    }
    if (lid < 16) {
        float4 v = p[768 + lid];
        s += (v.x + v.y) + (v.z + v.w);
    }
    #pragma unroll
    for (int off = 16; off > 0; off >>= 1)
        s += __shfl_xor_sync(0xFFFFFFFFu, s, off);
    if (lid == 0) g_y[plane] = s * (1.0f / (float)HW);
}

// ---------------------------------------------------------------------------
// Kernel 2: SE MLP + rank-select threshold + mask. One block per batch row.
// ---------------------------------------------------------------------------
__global__ void se_mask_kernel(const float* __restrict__ W1,   // [R, C]
                               const float* __restrict__ W2) { // [C, R]
    const int b = blockIdx.x;
    const int tid = threadIdx.x;
    __shared__ float sy[C];
    __shared__ float sh[R];
    __shared__ float sz[C];
    __shared__ float sthresh;

    sy[tid] = g_y[b * C + tid];
    __syncthreads();

    // hidden = relu(y @ W1^T): 8 warps, each computes 2 of the 16 rows
    const int wid = tid >> 5, lid = tid & 31;
    #pragma unroll
    for (int rr = 0; rr < 2; rr++) {
        const int row = wid * 2 + rr;
        float s = 0.f;
        for (int i = lid; i < C; i += 32)
            s += sy[i] * W1[row * C + i];
        #pragma unroll
        for (int off = 16; off > 0; off >>= 1)
            s += __shfl_xor_sync(0xFFFFFFFFu, s, off);
        if (lid == 0) sh[row] = fmaxf(s, 0.f);
    }
    __syncthreads();

    // z = sigmoid(hidden @ W2^T): one channel per thread
    float s = 0.f;
    #pragma unroll
    for (int k = 0; k < R; k++)
        s += sh[k] * W2[tid * R + k];
    const float z = 1.0f / (1.0f + __expf(-s));
    sz[tid] = z;
    __syncthreads();

    // rank-select: thresh = sorted[POSITION-1]. Element v is at 0-indexed
    // position 204 iff (#less < v) <= 204 and (#<= v) >= 205.
    int lt = 0, le = 0;
    for (int j = 0; j < C; j++) {
        const float zj = sz[j];
        lt += (zj < z);
        le += (zj <= z);
    }
    if (lt <= (POSITION - 1) && le >= POSITION) sthresh = z;
    __syncthreads();

    g_mask[b * C + tid] = (z <= sthresh) ? 1.0f : 0.0f;
}

// ---------------------------------------------------------------------------
// Kernel 3: out = x * mask[plane]. One block per plane, processed in REVERSE
// so the first waves hit the x-tail still resident in L2 from pool_kernel.
// Zero-mask planes skip the x read entirely (~20% of planes).
// ---------------------------------------------------------------------------
__global__ void apply_mask_kernel(const float* __restrict__ x,
                                  float* __restrict__ out) {
    const int plane = (NPLANES - 1) - blockIdx.x;
    const float m = g_mask[plane];
    const float4* __restrict__ px = (const float4*)(x + (size_t)plane * HW);
    float4* __restrict__ po = (float4*)(out + (size_t)plane * HW);
    const int tid = threadIdx.x;

    if (m == 0.0f) {
        const float4 z4 = make_float4(0.f, 0.f, 0.f, 0.f);
        #pragma unroll
        for (int k = 0; k < 3; k++)
            __stcs(&po[tid + 256 * k], z4);
        if (tid < 16)
            __stcs(&po[768 + tid], z4);
        return;
    }

    // 784 = 3*256 + 16
    #pragma unroll
    for (int k = 0; k < 3; k++) {
        const int i = tid + 256 * k;
        float4 v = __ldcs(&px[i]);
        v.x *= m; v.y *= m; v.z *= m; v.w *= m;
        __stcs(&po[i], v);
    }
    if (tid < 16) {
        const int i = 768 + tid;
        float4 v = __ldcs(&px[i]);
        v.x *= m; v.y *= m; v.z *= m; v.w *= m;
        __stcs(&po[i], v);
    }
}

// ---------------------------------------------------------------------------
extern "C" void kernel_launch(void* const* d_in, const int* in_sizes, int n_in,
                              void* d_out, int out_size) {
    const float* x  = (const float*)d_in[0];
    const float* W1 = (const float*)d_in[1];
    const float* W2 = (const float*)d_in[2];
    float* out = (float*)d_out;

    pool_kernel<<<NPLANES / 8, 256>>>(x);
    se_mask_kernel<<<B, C>>>(W1, W2);
    apply_mask_kernel<<<NPLANES, 256>>>(x, out);
}

// round 16
// speedup vs baseline: 1.3434x; 1.1406x over previous
#include <cuda_runtime.h>
#include <cuda_bf16.h>

// Problem constants (fixed shapes from reference)
#define B 64
#define C 256
#define HW 3136          // 56*56
#define HW4 784          // HW/4 float4 per plane
#define R 16             // reduced dim
#define POSITION 205     // round(0.8*256); thresh = sorted[POSITION-1] (0-idx 204)
#define NPLANES (B * C)

__device__ float g_y[B * C];     // pooled means
__device__ float g_mask[B * C];  // 0/1 mask

// ---------------------------------------------------------------------------
// Kernel 1: fused global-average-pool + copy. One WARP per (b,c) plane.
// Key identity: mask is exactly 0.0 or 1.0, and x*1.0f == x bit-for-bit, so
// kept planes' output is a pure copy of x. Copy EVERY plane here (single read
// of x), then a later write-only kernel zeroes the dropped planes.
// Streaming hints: neither stream is reused.
// ---------------------------------------------------------------------------
__global__ void pool_copy_kernel(const float* __restrict__ x,
                                 float* __restrict__ out) {
    const int wid = threadIdx.x >> 5, lid = threadIdx.x & 31;
    const int plane = blockIdx.x * 8 + wid;       // b*C + c
    const float4* __restrict__ p  = (const float4*)(x   + (size_t)plane * HW);
    float4* __restrict__       po = (float4*)      (out + (size_t)plane * HW);

    float s = 0.f;
    // 784 = 32*24 + 16
    #pragma unroll
    for (int k = 0; k < 24; k++) {
        const int i = lid + 32 * k;
        float4 v = __ldcs(&p[i]);
        s += (v.x + v.y) + (v.z + v.w);
        __stcs(&po[i], v);
    }
    if (lid < 16) {
        const int i = 768 + lid;
        float4 v = __ldcs(&p[i]);
        s += (v.x + v.y) + (v.z + v.w);
        __stcs(&po[i], v);
    }
    #pragma unroll
    for (int off = 16; off > 0; off >>= 1)
        s += __shfl_xor_sync(0xFFFFFFFFu, s, off);
    if (lid == 0) g_y[plane] = s * (1.0f / (float)HW);
}

// ---------------------------------------------------------------------------
// Kernel 2: SE MLP + rank-select threshold + mask. One block per batch row.
// ---------------------------------------------------------------------------
__global__ void se_mask_kernel(const float* __restrict__ W1,   // [R, C]
                               const float* __restrict__ W2) { // [C, R]
    const int b = blockIdx.x;
    const int tid = threadIdx.x;
    __shared__ float sy[C];
    __shared__ float sh[R];
    __shared__ float sz[C];
    __shared__ float sthresh;

    sy[tid] = g_y[b * C + tid];
    __syncthreads();

    // hidden = relu(y @ W1^T): 8 warps, each computes 2 of the 16 rows
    const int wid = tid >> 5, lid = tid & 31;
    #pragma unroll
    for (int rr = 0; rr < 2; rr++) {
        const int row = wid * 2 + rr;
        float s = 0.f;
        for (int i = lid; i < C; i += 32)
            s += sy[i] * W1[row * C + i];
        #pragma unroll
        for (int off = 16; off > 0; off >>= 1)
            s += __shfl_xor_sync(0xFFFFFFFFu, s, off);
        if (lid == 0) sh[row] = fmaxf(s, 0.f);
    }
    __syncthreads();

    // z = sigmoid(hidden @ W2^T): one channel per thread
    float s = 0.f;
    #pragma unroll
    for (int k = 0; k < R; k++)
        s += sh[k] * W2[tid * R + k];
    const float z = 1.0f / (1.0f + __expf(-s));
    sz[tid] = z;
    __syncthreads();

    // rank-select: thresh = sorted[POSITION-1]. Element v is at 0-indexed
    // position 204 iff (#less < v) <= 204 and (#<= v) >= 205.
    int lt = 0, le = 0;
    for (int j = 0; j < C; j++) {
        const float zj = sz[j];
        lt += (zj < z);
        le += (zj <= z);
    }
    if (lt <= (POSITION - 1) && le >= POSITION) sthresh = z;
    __syncthreads();

    g_mask[b * C + tid] = (z <= sthresh) ? 1.0f : 0.0f;
}

// ---------------------------------------------------------------------------
// Kernel 3: zero the dropped planes (mask==0, ~51/256). WRITE-ONLY: 41 MB.
// One block per plane; kept planes exit immediately.
// ---------------------------------------------------------------------------
__global__ void zero_planes_kernel(float* __restrict__ out) {
    const int plane = blockIdx.x;
    if (g_mask[plane] != 0.0f) return;

    float4* __restrict__ po = (float4*)(out + (size_t)plane * HW);
    const int tid = threadIdx.x;
    const float4 z4 = make_float4(0.f, 0.f, 0.f, 0.f);
    // 784 = 3*256 + 16
    #pragma unroll
    for (int k = 0; k < 3; k++)
        __stcs(&po[tid + 256 * k], z4);
    if (tid < 16)
        __stcs(&po[768 + tid], z4);
}

// ---------------------------------------------------------------------------
extern "C" void kernel_launch(void* const* d_in, const int* in_sizes, int n_in,
                              void* d_out, int out_size) {
    const float* x  = (const float*)d_in[0];
    const float* W1 = (const float*)d_in[1];
    const float* W2 = (const float*)d_in[2];
    float* out = (float*)d_out;

    pool_copy_kernel<<<NPLANES / 8, 256>>>(x, out);
    se_mask_kernel<<<B, C>>>(W1, W2);
    zero_planes_kernel<<<NPLANES, 256>>>(out);
}